// round 3
// baseline (speedup 1.0000x reference)
#include <cuda_runtime.h>
#include <math.h>

// Problem constants
#define BATCH 2
#define TLEN  2048
#define DM    1024
#define NH    16
#define DHD   64
#define BT    (BATCH * TLEN)   // 4096

// Scratch (allocation-free rule: __device__ globals)
__device__ float g_q[BT * DM];
__device__ float g_k[BT * DM];
__device__ float g_v[BT * DM];
__device__ float g_o[BT * DM];

// ---------------------------------------------------------------------------
// GEMM (NT): C[m,n] = sum_k A[m,k] * B[n,k]
// A: [M,K] row-major, B: [N,K] row-major, C: [M,N] row-major
// 128x128 block tile, BK=16, 256 threads, 8x8 register frags, smem prefetch.
// ---------------------------------------------------------------------------
#define GBM 128
#define GBN 128
#define GBK 16
#define ASTR 132   // padded stride (floats) to reduce transpose-store conflicts

#define STORE_SMEM(a0, a1, b0, b1)                                      \
    do {                                                                \
        As[(lf4 + 0) * ASTR + lrow]      = (a0).x;                      \
        As[(lf4 + 1) * ASTR + lrow]      = (a0).y;                      \
        As[(lf4 + 2) * ASTR + lrow]      = (a0).z;                      \
        As[(lf4 + 3) * ASTR + lrow]      = (a0).w;                      \
        As[(lf4 + 0) * ASTR + lrow + 64] = (a1).x;                      \
        As[(lf4 + 1) * ASTR + lrow + 64] = (a1).y;                      \
        As[(lf4 + 2) * ASTR + lrow + 64] = (a1).z;                      \
        As[(lf4 + 3) * ASTR + lrow + 64] = (a1).w;                      \
        Bs[(lf4 + 0) * ASTR + lrow]      = (b0).x;                      \
        Bs[(lf4 + 1) * ASTR + lrow]      = (b0).y;                      \
        Bs[(lf4 + 2) * ASTR + lrow]      = (b0).z;                      \
        Bs[(lf4 + 3) * ASTR + lrow]      = (b0).w;                      \
        Bs[(lf4 + 0) * ASTR + lrow + 64] = (b1).x;                      \
        Bs[(lf4 + 1) * ASTR + lrow + 64] = (b1).y;                      \
        Bs[(lf4 + 2) * ASTR + lrow + 64] = (b1).z;                      \
        Bs[(lf4 + 3) * ASTR + lrow + 64] = (b1).w;                      \
    } while (0)

__global__ __launch_bounds__(256)
void gemm_nt(const float* __restrict__ A, const float* __restrict__ B,
             float* __restrict__ C, int M, int N, int K)
{
    __shared__ float As[GBK * ASTR];
    __shared__ float Bs[GBK * ASTR];

    const int tid = threadIdx.x;
    const int tx  = tid & 15;
    const int ty  = tid >> 4;
    const int m0  = blockIdx.y * GBM;
    const int n0  = blockIdx.x * GBN;

    // loader mapping: 256 threads, each loads 2 float4 from A and 2 from B per tile
    const int lrow = tid >> 2;          // 0..63 (covers rows, +64 for second half)
    const int lf4  = (tid & 3) << 2;    // k offset within BK: 0,4,8,12

    const float* Ab = A + (m0 + lrow) * K + lf4;
    const float* Bb = B + (n0 + lrow) * K + lf4;

    float acc[8][8];
#pragma unroll
    for (int i = 0; i < 8; i++)
#pragma unroll
        for (int j = 0; j < 8; j++) acc[i][j] = 0.0f;

    // prefetch tile 0
    float4 ra0 = *(const float4*)(Ab);
    float4 ra1 = *(const float4*)(Ab + 64 * K);
    float4 rb0 = *(const float4*)(Bb);
    float4 rb1 = *(const float4*)(Bb + 64 * K);
    STORE_SMEM(ra0, ra1, rb0, rb1);
    __syncthreads();

    const int nkt = K >> 4;
    for (int kt = 0; kt < nkt; kt++) {
        float4 na0, na1, nb0, nb1;
        if (kt + 1 < nkt) {
            const float* Ap = Ab + (kt + 1) * GBK;
            const float* Bp = Bb + (kt + 1) * GBK;
            na0 = *(const float4*)(Ap);
            na1 = *(const float4*)(Ap + 64 * K);
            nb0 = *(const float4*)(Bp);
            nb1 = *(const float4*)(Bp + 64 * K);
        }
#pragma unroll
        for (int k = 0; k < GBK; k++) {
            float a[8], b[8];
            *(float4*)&a[0] = *(const float4*)&As[k * ASTR + ty * 8];
            *(float4*)&a[4] = *(const float4*)&As[k * ASTR + ty * 8 + 4];
            *(float4*)&b[0] = *(const float4*)&Bs[k * ASTR + tx * 8];
            *(float4*)&b[4] = *(const float4*)&Bs[k * ASTR + tx * 8 + 4];
#pragma unroll
            for (int i = 0; i < 8; i++)
#pragma unroll
                for (int j = 0; j < 8; j++)
                    acc[i][j] = fmaf(a[i], b[j], acc[i][j]);
        }
        __syncthreads();
        if (kt + 1 < nkt) {
            STORE_SMEM(na0, na1, nb0, nb1);
            __syncthreads();
        }
    }

#pragma unroll
    for (int i = 0; i < 8; i++) {
        float* Cp = C + (m0 + ty * 8 + i) * N + n0 + tx * 8;
        float4 c0 = make_float4(acc[i][0], acc[i][1], acc[i][2], acc[i][3]);
        float4 c1 = make_float4(acc[i][4], acc[i][5], acc[i][6], acc[i][7]);
        *(float4*)(Cp)     = c0;
        *(float4*)(Cp + 4) = c1;
    }
}

// ---------------------------------------------------------------------------
// Flash attention: per (b, h, q-tile of 64 rows), stream KV in 64-row tiles.
// 256 threads as 16x16: rows = ty*4+i (i<4), cols = tx + 16*j (j<4, STRIDED
// fragmentation -> bank indices spread over tx, keeping LDS near conflict-free).
// Online softmax with per-row running (m, l) replicated across the 16-thread
// row group via butterfly shuffles.
// ---------------------------------------------------------------------------
#define FPAD 68   // padded row stride (floats), keeps float4 alignment

#define DOT4(qv, kv) ((qv).x * (kv).x + (qv).y * (kv).y + (qv).z * (kv).z + (qv).w * (kv).w)

#define SROW(i, qv)                       \
    s[i][0] += DOT4(qv, k0v);             \
    s[i][1] += DOT4(qv, k1v);             \
    s[i][2] += DOT4(qv, k2v);             \
    s[i][3] += DOT4(qv, k3v);

#define PV_U(comp, off)                                                     \
    do {                                                                    \
        const float* vr = &Vs[(j4 * 4 + (off)) * FPAD + tx];                \
        float v0 = vr[0], v1 = vr[16], v2 = vr[32], v3 = vr[48];            \
        o[0][0] = fmaf(p0.comp, v0, o[0][0]);                               \
        o[0][1] = fmaf(p0.comp, v1, o[0][1]);                               \
        o[0][2] = fmaf(p0.comp, v2, o[0][2]);                               \
        o[0][3] = fmaf(p0.comp, v3, o[0][3]);                               \
        o[1][0] = fmaf(p1.comp, v0, o[1][0]);                               \
        o[1][1] = fmaf(p1.comp, v1, o[1][1]);                               \
        o[1][2] = fmaf(p1.comp, v2, o[1][2]);                               \
        o[1][3] = fmaf(p1.comp, v3, o[1][3]);                               \
        o[2][0] = fmaf(p2.comp, v0, o[2][0]);                               \
        o[2][1] = fmaf(p2.comp, v1, o[2][1]);                               \
        o[2][2] = fmaf(p2.comp, v2, o[2][2]);                               \
        o[2][3] = fmaf(p2.comp, v3, o[2][3]);                               \
        o[3][0] = fmaf(p3.comp, v0, o[3][0]);                               \
        o[3][1] = fmaf(p3.comp, v1, o[3][1]);                               \
        o[3][2] = fmaf(p3.comp, v2, o[3][2]);                               \
        o[3][3] = fmaf(p3.comp, v3, o[3][3]);                               \
    } while (0)

__global__ __launch_bounds__(256)
void flash_attn(const float* __restrict__ Q, const float* __restrict__ K,
                const float* __restrict__ V, float* __restrict__ O)
{
    extern __shared__ float sm[];
    float* Qs = sm;                  // [64][FPAD]
    float* Ks = sm + 64 * FPAD;      // [64][FPAD]
    float* Vs = sm + 2 * 64 * FPAD;  // [64][FPAD]
    float* Ps = sm + 3 * 64 * FPAD;  // [64][FPAD]

    const int tid = threadIdx.x;
    const int tx  = tid & 15;
    const int ty  = tid >> 4;
    const int q0  = blockIdx.x * 64;
    const int h   = blockIdx.y;
    const int b   = blockIdx.z;
    const int base = b * TLEN * DM + h * DHD;  // add row*DM + d

    // load Q tile (64 x 64), coalesced float4
#pragma unroll
    for (int it = 0; it < 4; it++) {
        int f4 = tid + it * 256;
        int r  = f4 >> 4;
        int c4 = (f4 & 15) << 2;
        *(float4*)&Qs[r * FPAD + c4] =
            *(const float4*)(Q + base + (q0 + r) * DM + c4);
    }

    float m_run[4], l_run[4], o[4][4];
#pragma unroll
    for (int i = 0; i < 4; i++) {
        m_run[i] = -1e30f;
        l_run[i] = 0.0f;
#pragma unroll
        for (int j = 0; j < 4; j++) o[i][j] = 0.0f;
    }

    const float scale = 0.125f;  // 1/sqrt(64)

    for (int t = 0; t < TLEN / 64; t++) {
        __syncthreads();  // prior PV reads of Vs done
        const int kv0 = t * 64;
#pragma unroll
        for (int it = 0; it < 4; it++) {
            int f4 = tid + it * 256;
            int r  = f4 >> 4;
            int c4 = (f4 & 15) << 2;
            *(float4*)&Ks[r * FPAD + c4] =
                *(const float4*)(K + base + (kv0 + r) * DM + c4);
            *(float4*)&Vs[r * FPAD + c4] =
                *(const float4*)(V + base + (kv0 + r) * DM + c4);
        }
        __syncthreads();

        // S = Q K^T  (4x4 frag per thread, dot over d in float4 steps)
        float s[4][4];
#pragma unroll
        for (int i = 0; i < 4; i++)
#pragma unroll
            for (int j = 0; j < 4; j++) s[i][j] = 0.0f;

#pragma unroll
        for (int d4 = 0; d4 < 16; d4++) {
            float4 q0v = *(const float4*)&Qs[(ty * 4 + 0) * FPAD + d4 * 4];
            float4 q1v = *(const float4*)&Qs[(ty * 4 + 1) * FPAD + d4 * 4];
            float4 q2v = *(const float4*)&Qs[(ty * 4 + 2) * FPAD + d4 * 4];
            float4 q3v = *(const float4*)&Qs[(ty * 4 + 3) * FPAD + d4 * 4];
            float4 k0v = *(const float4*)&Ks[(tx +  0) * FPAD + d4 * 4];
            float4 k1v = *(const float4*)&Ks[(tx + 16) * FPAD + d4 * 4];
            float4 k2v = *(const float4*)&Ks[(tx + 32) * FPAD + d4 * 4];
            float4 k3v = *(const float4*)&Ks[(tx + 48) * FPAD + d4 * 4];
            SROW(0, q0v)
            SROW(1, q1v)
            SROW(2, q2v)
            SROW(3, q3v)
        }

        // online softmax per row (row group = 16 threads sharing ty)
#pragma unroll
        for (int i = 0; i < 4; i++) {
            float tmax = -1e30f;
#pragma unroll
            for (int j = 0; j < 4; j++) {
                s[i][j] *= scale;
                tmax = fmaxf(tmax, s[i][j]);
            }
#pragma unroll
            for (int msk = 1; msk < 16; msk <<= 1)
                tmax = fmaxf(tmax, __shfl_xor_sync(0xffffffffu, tmax, msk));
            float newm = fmaxf(m_run[i], tmax);
            float fac  = __expf(m_run[i] - newm);
            float tsum = 0.0f;
#pragma unroll
            for (int j = 0; j < 4; j++) {
                float p = __expf(s[i][j] - newm);
                tsum += p;
                Ps[(ty * 4 + i) * FPAD + tx + 16 * j] = p;
            }
#pragma unroll
            for (int msk = 1; msk < 16; msk <<= 1)
                tsum += __shfl_xor_sync(0xffffffffu, tsum, msk);
            l_run[i] = l_run[i] * fac + tsum;
            m_run[i] = newm;
#pragma unroll
            for (int j = 0; j < 4; j++) o[i][j] *= fac;
        }
        __syncthreads();  // Ps visible to all

        // O += P V  (dot over kv index jj in float4 steps for P)
#pragma unroll
        for (int j4 = 0; j4 < 16; j4++) {
            float4 p0 = *(const float4*)&Ps[(ty * 4 + 0) * FPAD + j4 * 4];
            float4 p1 = *(const float4*)&Ps[(ty * 4 + 1) * FPAD + j4 * 4];
            float4 p2 = *(const float4*)&Ps[(ty * 4 + 2) * FPAD + j4 * 4];
            float4 p3 = *(const float4*)&Ps[(ty * 4 + 3) * FPAD + j4 * 4];
            PV_U(x, 0);
            PV_U(y, 1);
            PV_U(z, 2);
            PV_U(w, 3);
        }
    }

    // epilogue: normalize and store (strided cols -> fully coalesced scalars)
#pragma unroll
    for (int i = 0; i < 4; i++) {
        float inv = 1.0f / l_run[i];
        float* Op = O + base + (q0 + ty * 4 + i) * DM;
#pragma unroll
        for (int j = 0; j < 4; j++)
            Op[tx + 16 * j] = o[i][j] * inv;
    }
}

// ---------------------------------------------------------------------------
// Launch: 3 QKV GEMMs -> flash attention -> output GEMM. Graph-capturable:
// kernel launches only, no allocs, no syncs.
// ---------------------------------------------------------------------------
extern "C" void kernel_launch(void* const* d_in, const int* in_sizes, int n_in,
                              void* d_out, int out_size)
{
    (void)in_sizes; (void)n_in; (void)out_size;
    const float* x  = (const float*)d_in[0];
    const float* Wq = (const float*)d_in[1];
    const float* Wk = (const float*)d_in[2];
    const float* Wv = (const float*)d_in[3];
    const float* Wo = (const float*)d_in[4];
    float* out = (float*)d_out;

    float *q, *k, *v, *o;
    cudaGetSymbolAddress((void**)&q, g_q);
    cudaGetSymbolAddress((void**)&k, g_k);
    cudaGetSymbolAddress((void**)&v, g_v);
    cudaGetSymbolAddress((void**)&o, g_o);

    dim3 gg(DM / GBN, BT / GBM);  // (8, 32)
    gemm_nt<<<gg, 256>>>(x, Wq, q, BT, DM, DM);
    gemm_nt<<<gg, 256>>>(x, Wk, k, BT, DM, DM);
    gemm_nt<<<gg, 256>>>(x, Wv, v, BT, DM, DM);

    const int smem = 4 * 64 * FPAD * (int)sizeof(float);  // 69632 B
    cudaFuncSetAttribute(flash_attn, cudaFuncAttributeMaxDynamicSharedMemorySize, smem);
    flash_attn<<<dim3(TLEN / 64, NH, BATCH), 256, smem>>>(q, k, v, o);

    gemm_nt<<<gg, 256>>>(o, Wo, out, BT, DM, DM);
}

// round 7
// speedup vs baseline: 1.4518x; 1.4518x over previous
#include <cuda_runtime.h>
#include <stdint.h>
#include <stddef.h>
#include <math.h>

#define BATCH 2
#define TLEN  2048
#define DM    1024
#define NH    16
#define DHD   64
#define BT    (BATCH * TLEN)   // 4096

// ---------------------------------------------------------------------------
// Scratch (allocation-free rule: __device__ globals)
// ---------------------------------------------------------------------------
__device__ float g_q[BT * DM];
__device__ float g_k[BT * DM];
__device__ float g_v[BT * DM];
__device__ float g_o[BT * DM];
__device__ float g_xc[BT * DM];
__device__ float g_wq[DM * DM];
__device__ float g_wk[DM * DM];
__device__ float g_wv[DM * DM];
__device__ float g_wo[DM * DM];

// ---------------------------------------------------------------------------
// Helpers
// ---------------------------------------------------------------------------
__device__ __forceinline__ float f2tf32(float x) {
    uint32_t u;
    asm("cvt.rna.tf32.f32 %0, %1;" : "=r"(u) : "f"(x));
    return __uint_as_float(u);
}

__device__ __forceinline__ void cp16(uint32_t smem, const void* gmem) {
    asm volatile("cp.async.cg.shared.global [%0], [%1], 16;"
                 :: "r"(smem), "l"(gmem));
}
#define CP_COMMIT() asm volatile("cp.async.commit_group;")
#define CP_WAIT0()  asm volatile("cp.async.wait_group 0;")
#define CP_WAIT1()  asm volatile("cp.async.wait_group 1;")

// mma.sync m16n8k8 tf32: D(f32) = A(tf32) * B(tf32) + D
#define MMA_TF32(d, a, b)                                                   \
    asm volatile(                                                           \
        "mma.sync.aligned.m16n8k8.row.col.f32.tf32.tf32.f32 "               \
        "{%0,%1,%2,%3},{%4,%5,%6,%7},{%8,%9},{%0,%1,%2,%3};"                \
        : "+f"((d)[0]), "+f"((d)[1]), "+f"((d)[2]), "+f"((d)[3])            \
        : "r"((a)[0]), "r"((a)[1]), "r"((a)[2]), "r"((a)[3]),               \
          "r"((b)[0]), "r"((b)[1]))

// ---------------------------------------------------------------------------
// Prep: round fp32 -> tf32 (RN) into scratch
// ---------------------------------------------------------------------------
__global__ void cvt_tf32_kernel(const float4* __restrict__ in,
                                float4* __restrict__ out, int n4) {
    int i = blockIdx.x * blockDim.x + threadIdx.x;
    if (i < n4) {
        float4 v = in[i];
        v.x = f2tf32(v.x); v.y = f2tf32(v.y);
        v.z = f2tf32(v.z); v.w = f2tf32(v.w);
        out[i] = v;
    }
}

// ---------------------------------------------------------------------------
// tf32 GEMM (NT): C[m,n] = sum_k A[m,k] * B[n,k]
// 128x128 block, 4 warps (2x2) of 64x64, BK=32, cp.async double-buffered.
// ---------------------------------------------------------------------------
#define GS   36
#define GBUF (128 * GS)

template <bool CVT_OUT>
__global__ __launch_bounds__(128)
void gemm_tf32(const float* __restrict__ A, const float* __restrict__ B,
               float* __restrict__ C, int M, int N, int K)
{
    extern __shared__ float sm[];
    float* As = sm;               // [2][GBUF]
    float* Bs = sm + 2 * GBUF;    // [2][GBUF]

    const int tid  = threadIdx.x;
    const int lane = tid & 31;
    const int warp = tid >> 5;
    const int g    = lane >> 2;
    const int t    = lane & 3;
    const int m0   = blockIdx.y * 128;
    const int n0   = blockIdx.x * 128;
    const int mw   = (warp >> 1) * 64;
    const int nw   = (warp & 1) * 64;

    const int lr = tid >> 3;           // 0..15
    const int lc = (tid & 7) << 2;     // 0,4,...,28
    const float* Ag = A + (size_t)(m0 + lr) * K + lc;
    const float* Bg = B + (size_t)(n0 + lr) * K + lc;

    const uint32_t sA = (uint32_t)__cvta_generic_to_shared(As);
    const uint32_t sB = (uint32_t)__cvta_generic_to_shared(Bs);
    const uint32_t soff = (uint32_t)(lr * GS + lc) * 4u;

    float acc[4][8][4];
#pragma unroll
    for (int mt = 0; mt < 4; mt++)
#pragma unroll
        for (int nt = 0; nt < 8; nt++)
#pragma unroll
            for (int r = 0; r < 4; r++) acc[mt][nt][r] = 0.0f;

    const int nkt = K >> 5;

#pragma unroll
    for (int i = 0; i < 8; i++) {
        cp16(sA + soff + (uint32_t)(i * 16 * GS * 4), Ag + (size_t)i * 16 * K);
        cp16(sB + soff + (uint32_t)(i * 16 * GS * 4), Bg + (size_t)i * 16 * K);
    }
    CP_COMMIT();

    for (int kt = 0; kt < nkt; kt++) {
        const int cur = kt & 1;
        if (kt + 1 < nkt) {
            const int nxt = cur ^ 1;
            const float* Ap = Ag + (size_t)(kt + 1) * 32;
            const float* Bp = Bg + (size_t)(kt + 1) * 32;
            const uint32_t bufo = (uint32_t)(nxt * GBUF * 4);
#pragma unroll
            for (int i = 0; i < 8; i++) {
                cp16(sA + bufo + soff + (uint32_t)(i * 16 * GS * 4), Ap + (size_t)i * 16 * K);
                cp16(sB + bufo + soff + (uint32_t)(i * 16 * GS * 4), Bp + (size_t)i * 16 * K);
            }
            CP_COMMIT();
            CP_WAIT1();
        } else {
            CP_WAIT0();
        }
        __syncthreads();

        const float* Ab = As + cur * GBUF + mw * GS;
        const float* Bb = Bs + cur * GBUF + nw * GS;
#pragma unroll
        for (int kc = 0; kc < 4; kc++) {
            const int kk = kc * 8;
            uint32_t af[4][4], bf[8][2];
#pragma unroll
            for (int mt = 0; mt < 4; mt++) {
                const float* p = Ab + (mt * 16 + g) * GS + kk + t;
                af[mt][0] = __float_as_uint(p[0]);
                af[mt][1] = __float_as_uint(p[8 * GS]);
                af[mt][2] = __float_as_uint(p[4]);
                af[mt][3] = __float_as_uint(p[8 * GS + 4]);
            }
#pragma unroll
            for (int nt = 0; nt < 8; nt++) {
                const float* p = Bb + (nt * 8 + g) * GS + kk + t;
                bf[nt][0] = __float_as_uint(p[0]);
                bf[nt][1] = __float_as_uint(p[4]);
            }
#pragma unroll
            for (int mt = 0; mt < 4; mt++)
#pragma unroll
                for (int nt = 0; nt < 8; nt++)
                    MMA_TF32(acc[mt][nt], af[mt], bf[nt]);
        }
        __syncthreads();
    }

#pragma unroll
    for (int mt = 0; mt < 4; mt++) {
#pragma unroll
        for (int nt = 0; nt < 8; nt++) {
            const int row = m0 + mw + mt * 16 + g;
            const int col = n0 + nw + nt * 8 + 2 * t;
            float2 v0, v1;
            if (CVT_OUT) {
                v0 = make_float2(f2tf32(acc[mt][nt][0]), f2tf32(acc[mt][nt][1]));
                v1 = make_float2(f2tf32(acc[mt][nt][2]), f2tf32(acc[mt][nt][3]));
            } else {
                v0 = make_float2(acc[mt][nt][0], acc[mt][nt][1]);
                v1 = make_float2(acc[mt][nt][2], acc[mt][nt][3]);
            }
            *(float2*)&C[(size_t)row * N + col]       = v0;
            *(float2*)&C[(size_t)(row + 8) * N + col] = v1;
        }
    }
}

// ---------------------------------------------------------------------------
// Flash attention — KNOWN-GOOD R3 SIMT version, verbatim.
// ---------------------------------------------------------------------------
#define FPAD 68

#define DOT4(qv, kv) ((qv).x * (kv).x + (qv).y * (kv).y + (qv).z * (kv).z + (qv).w * (kv).w)

#define SROW(i, qv)                       \
    s[i][0] += DOT4(qv, k0v);             \
    s[i][1] += DOT4(qv, k1v);             \
    s[i][2] += DOT4(qv, k2v);             \
    s[i][3] += DOT4(qv, k3v);

#define PV_U(comp, off)                                                     \
    do {                                                                    \
        const float* vr = &Vs[(j4 * 4 + (off)) * FPAD + tx];                \
        float v0 = vr[0], v1 = vr[16], v2 = vr[32], v3 = vr[48];            \
        o[0][0] = fmaf(p0.comp, v0, o[0][0]);                               \
        o[0][1] = fmaf(p0.comp, v1, o[0][1]);                               \
        o[0][2] = fmaf(p0.comp, v2, o[0][2]);                               \
        o[0][3] = fmaf(p0.comp, v3, o[0][3]);                               \
        o[1][0] = fmaf(p1.comp, v0, o[1][0]);                               \
        o[1][1] = fmaf(p1.comp, v1, o[1][1]);                               \
        o[1][2] = fmaf(p1.comp, v2, o[1][2]);                               \
        o[1][3] = fmaf(p1.comp, v3, o[1][3]);                               \
        o[2][0] = fmaf(p2.comp, v0, o[2][0]);                               \
        o[2][1] = fmaf(p2.comp, v1, o[2][1]);                               \
        o[2][2] = fmaf(p2.comp, v2, o[2][2]);                               \
        o[2][3] = fmaf(p2.comp, v3, o[2][3]);                               \
        o[3][0] = fmaf(p3.comp, v0, o[3][0]);                               \
        o[3][1] = fmaf(p3.comp, v1, o[3][1]);                               \
        o[3][2] = fmaf(p3.comp, v2, o[3][2]);                               \
        o[3][3] = fmaf(p3.comp, v3, o[3][3]);                               \
    } while (0)

__global__ __launch_bounds__(256)
void flash_attn(const float* __restrict__ Q, const float* __restrict__ K,
                const float* __restrict__ V, float* __restrict__ O)
{
    extern __shared__ float sm[];
    float* Qs = sm;                  // [64][FPAD]
    float* Ks = sm + 64 * FPAD;      // [64][FPAD]
    float* Vs = sm + 2 * 64 * FPAD;  // [64][FPAD]
    float* Ps = sm + 3 * 64 * FPAD;  // [64][FPAD]

    const int tid = threadIdx.x;
    const int tx  = tid & 15;
    const int ty  = tid >> 4;
    const int q0  = blockIdx.x * 64;
    const int h   = blockIdx.y;
    const int b   = blockIdx.z;
    const int base = b * TLEN * DM + h * DHD;

#pragma unroll
    for (int it = 0; it < 4; it++) {
        int f4 = tid + it * 256;
        int r  = f4 >> 4;
        int c4 = (f4 & 15) << 2;
        *(float4*)&Qs[r * FPAD + c4] =
            *(const float4*)(Q + base + (q0 + r) * DM + c4);
    }

    float m_run[4], l_run[4], o[4][4];
#pragma unroll
    for (int i = 0; i < 4; i++) {
        m_run[i] = -1e30f;
        l_run[i] = 0.0f;
#pragma unroll
        for (int j = 0; j < 4; j++) o[i][j] = 0.0f;
    }

    const float scale = 0.125f;

    for (int t = 0; t < TLEN / 64; t++) {
        __syncthreads();
        const int kv0 = t * 64;
#pragma unroll
        for (int it = 0; it < 4; it++) {
            int f4 = tid + it * 256;
            int r  = f4 >> 4;
            int c4 = (f4 & 15) << 2;
            *(float4*)&Ks[r * FPAD + c4] =
                *(const float4*)(K + base + (kv0 + r) * DM + c4);
            *(float4*)&Vs[r * FPAD + c4] =
                *(const float4*)(V + base + (kv0 + r) * DM + c4);
        }
        __syncthreads();

        float s[4][4];
#pragma unroll
        for (int i = 0; i < 4; i++)
#pragma unroll
            for (int j = 0; j < 4; j++) s[i][j] = 0.0f;

#pragma unroll
        for (int d4 = 0; d4 < 16; d4++) {
            float4 q0v = *(const float4*)&Qs[(ty * 4 + 0) * FPAD + d4 * 4];
            float4 q1v = *(const float4*)&Qs[(ty * 4 + 1) * FPAD + d4 * 4];
            float4 q2v = *(const float4*)&Qs[(ty * 4 + 2) * FPAD + d4 * 4];
            float4 q3v = *(const float4*)&Qs[(ty * 4 + 3) * FPAD + d4 * 4];
            float4 k0v = *(const float4*)&Ks[(tx +  0) * FPAD + d4 * 4];
            float4 k1v = *(const float4*)&Ks[(tx + 16) * FPAD + d4 * 4];
            float4 k2v = *(const float4*)&Ks[(tx + 32) * FPAD + d4 * 4];
            float4 k3v = *(const float4*)&Ks[(tx + 48) * FPAD + d4 * 4];
            SROW(0, q0v)
            SROW(1, q1v)
            SROW(2, q2v)
            SROW(3, q3v)
        }

#pragma unroll
        for (int i = 0; i < 4; i++) {
            float tmax = -1e30f;
#pragma unroll
            for (int j = 0; j < 4; j++) {
                s[i][j] *= scale;
                tmax = fmaxf(tmax, s[i][j]);
            }
#pragma unroll
            for (int msk = 1; msk < 16; msk <<= 1)
                tmax = fmaxf(tmax, __shfl_xor_sync(0xffffffffu, tmax, msk));
            float newm = fmaxf(m_run[i], tmax);
            float fac  = __expf(m_run[i] - newm);
            float tsum = 0.0f;
#pragma unroll
            for (int j = 0; j < 4; j++) {
                float p = __expf(s[i][j] - newm);
                tsum += p;
                Ps[(ty * 4 + i) * FPAD + tx + 16 * j] = p;
            }
#pragma unroll
            for (int msk = 1; msk < 16; msk <<= 1)
                tsum += __shfl_xor_sync(0xffffffffu, tsum, msk);
            l_run[i] = l_run[i] * fac + tsum;
            m_run[i] = newm;
#pragma unroll
            for (int j = 0; j < 4; j++) o[i][j] *= fac;
        }
        __syncthreads();

#pragma unroll
        for (int j4 = 0; j4 < 16; j4++) {
            float4 p0 = *(const float4*)&Ps[(ty * 4 + 0) * FPAD + j4 * 4];
            float4 p1 = *(const float4*)&Ps[(ty * 4 + 1) * FPAD + j4 * 4];
            float4 p2 = *(const float4*)&Ps[(ty * 4 + 2) * FPAD + j4 * 4];
            float4 p3 = *(const float4*)&Ps[(ty * 4 + 3) * FPAD + j4 * 4];
            PV_U(x, 0);
            PV_U(y, 1);
            PV_U(z, 2);
            PV_U(w, 3);
        }
    }

#pragma unroll
    for (int i = 0; i < 4; i++) {
        float inv = 1.0f / l_run[i];
        float* Op = O + base + (q0 + ty * 4 + i) * DM;
#pragma unroll
        for (int j = 0; j < 4; j++)
            Op[tx + 16 * j] = o[i][j] * inv;
    }
}

// ---------------------------------------------------------------------------
// Launch: cvt prep -> 3 tf32 GEMMs -> SIMT flash -> tf32 output GEMM
// ---------------------------------------------------------------------------
extern "C" void kernel_launch(void* const* d_in, const int* in_sizes, int n_in,
                              void* d_out, int out_size)
{
    (void)in_sizes; (void)n_in; (void)out_size;
    const float* x  = (const float*)d_in[0];
    const float* Wq = (const float*)d_in[1];
    const float* Wk = (const float*)d_in[2];
    const float* Wv = (const float*)d_in[3];
    const float* Wo = (const float*)d_in[4];
    float* out = (float*)d_out;

    float *q, *k, *v, *o, *xc, *wq, *wk, *wv, *wo;
    cudaGetSymbolAddress((void**)&q,  g_q);
    cudaGetSymbolAddress((void**)&k,  g_k);
    cudaGetSymbolAddress((void**)&v,  g_v);
    cudaGetSymbolAddress((void**)&o,  g_o);
    cudaGetSymbolAddress((void**)&xc, g_xc);
    cudaGetSymbolAddress((void**)&wq, g_wq);
    cudaGetSymbolAddress((void**)&wk, g_wk);
    cudaGetSymbolAddress((void**)&wv, g_wv);
    cudaGetSymbolAddress((void**)&wo, g_wo);

    const int gemm_smem = 4 * GBUF * (int)sizeof(float);  // 73728
    cudaFuncSetAttribute(gemm_tf32<true>,
                         cudaFuncAttributeMaxDynamicSharedMemorySize, gemm_smem);
    cudaFuncSetAttribute(gemm_tf32<false>,
                         cudaFuncAttributeMaxDynamicSharedMemorySize, gemm_smem);

    cvt_tf32_kernel<<<(BT * DM / 4 + 255) / 256, 256>>>((const float4*)x,  (float4*)xc, BT * DM / 4);
    cvt_tf32_kernel<<<(DM * DM / 4 + 255) / 256, 256>>>((const float4*)Wq, (float4*)wq, DM * DM / 4);
    cvt_tf32_kernel<<<(DM * DM / 4 + 255) / 256, 256>>>((const float4*)Wk, (float4*)wk, DM * DM / 4);
    cvt_tf32_kernel<<<(DM * DM / 4 + 255) / 256, 256>>>((const float4*)Wv, (float4*)wv, DM * DM / 4);
    cvt_tf32_kernel<<<(DM * DM / 4 + 255) / 256, 256>>>((const float4*)Wo, (float4*)wo, DM * DM / 4);

    dim3 gg(DM / 128, BT / 128);  // (8, 32)
    gemm_tf32<true><<<gg, 128, gemm_smem>>>(xc, wq, q, BT, DM, DM);
    gemm_tf32<true><<<gg, 128, gemm_smem>>>(xc, wk, k, BT, DM, DM);
    gemm_tf32<true><<<gg, 128, gemm_smem>>>(xc, wv, v, BT, DM, DM);

    const int fl_smem = 4 * 64 * FPAD * (int)sizeof(float);  // 69632
    cudaFuncSetAttribute(flash_attn, cudaFuncAttributeMaxDynamicSharedMemorySize, fl_smem);
    flash_attn<<<dim3(TLEN / 64, NH, BATCH), 256, fl_smem>>>(q, k, v, o);

    gemm_tf32<false><<<gg, 128, gemm_smem>>>(o, wo, out, BT, DM, DM);
}